// round 8
// baseline (speedup 1.0000x reference)
#include <cuda_runtime.h>
#include <math.h>

#define S   512
#define B   64
#define H   256
#define NH  4
#define NHH 1024      // NH*H
#define NCTA 128

// ---------------- device globals (no runtime allocation allowed) ------------
__device__ float g_P[(size_t)S * H * B];       // [t][j][b]  : x@Wi.T
__device__ float g_gate[(size_t)S * B * NH];   // [t][b][nh] : sigmoid gates
__device__ float g_cand[2][H * B];             // double-buffered cand, [j][b]
__device__ float g_sel[B * NHH];               // hcat at t = len-1
__device__ __align__(16) unsigned g_flags[NCTA];  // per-CTA barrier flags

// ---------------- init: reset barrier state each replay ---------------------
__global__ void init_kernel() {
    int i = threadIdx.x;
    if (i < NCTA) g_flags[i] = 0u;
}

// ---------------- gate precompute: g = sigmoid(d - 3*nh) --------------------
__global__ __launch_bounds__(256)
void gate_kernel(const float* __restrict__ fix_src) {
    int t = blockIdx.x;
    int tid = threadIdx.x;          // b = tid>>2, nh = tid&3
    int b = tid >> 2, nh = tid & 3;
    float d = fix_src[b * S + t];
    g_gate[(size_t)t * (B * NH) + tid] = 1.0f / (1.0f + expf(3.0f * (float)nh - d));
}

// ---------------- P precompute: P[t][j][b] = emb[src[b,t]] . Wi[j,:] --------
__global__ __launch_bounds__(256, 2)
void p_kernel(const int* __restrict__ src, const float* __restrict__ emb,
              const float* __restrict__ Wi) {
    __shared__ float s_x[32][256];
    __shared__ int s_tok[32];
    const int t = blockIdx.x >> 1, bh = blockIdx.x & 1;
    const int tid = threadIdx.x;

    if (tid < 32) s_tok[tid] = src[(bh * 32 + tid) * S + t];
    __syncthreads();
    {
        int row = tid >> 3, seg = tid & 7;
        const float4* sp = (const float4*)(emb + (size_t)s_tok[row] * H) + seg * 8;
        float4* dp = (float4*)(&s_x[row][0]) + seg * 8;
        #pragma unroll
        for (int q = 0; q < 8; ++q) dp[q] = sp[q];
    }
    __syncthreads();

    float acc[32];
    #pragma unroll
    for (int m = 0; m < 32; ++m) acc[m] = 0.0f;
    const int j = tid;
    const float4* w4p = (const float4*)(Wi + (size_t)j * H);

    #pragma unroll 2
    for (int k4 = 0; k4 < 64; ++k4) {
        float4 wv = w4p[k4];
        #pragma unroll
        for (int m = 0; m < 32; ++m) {
            float4 xv = *(const float4*)&s_x[m][k4 * 4];
            acc[m] = fmaf(wv.x, xv.x, acc[m]);
            acc[m] = fmaf(wv.y, xv.y, acc[m]);
            acc[m] = fmaf(wv.z, xv.z, acc[m]);
            acc[m] = fmaf(wv.w, xv.w, acc[m]);
        }
    }
    float* out = g_P + (size_t)t * (H * B) + (size_t)j * B + bh * 32;
    #pragma unroll
    for (int m4 = 0; m4 < 8; ++m4)
        ((float4*)out)[m4] = make_float4(acc[m4 * 4], acc[m4 * 4 + 1],
                                         acc[m4 * 4 + 2], acc[m4 * 4 + 3]);
}

// ---------------- parallel-flag grid barrier (32 vector pollers) ------------
__device__ __forceinline__ void grid_barrier(unsigned& bcnt, int tid, int cid) {
    __syncthreads();                      // CTA arrival; cta-scope hb to tid0
    ++bcnt;
    if (tid == 0)
        asm volatile("st.release.gpu.global.u32 [%0], %1;"
                     :: "l"(&g_flags[cid]), "r"(bcnt) : "memory");
    if (tid < 32) {
        const uint4* fp = (const uint4*)g_flags;
        uint4 f;
        do {
            asm volatile("ld.volatile.global.v4.u32 {%0,%1,%2,%3}, [%4];"
                         : "=r"(f.x), "=r"(f.y), "=r"(f.z), "=r"(f.w)
                         : "l"(fp + tid) : "memory");
        } while (f.x < bcnt || f.y < bcnt || f.z < bcnt || f.w < bcnt);
        unsigned acq;
        asm volatile("ld.acquire.gpu.global.u32 %0, [%1];"
                     : "=r"(acq) : "l"(&g_flags[0]) : "memory");
    }
    __syncthreads();                      // release CTA
}

// ---------------- persistent recurrent kernel -------------------------------
// 128 CTAs, CTA c owns output columns j = {2c, 2c+1}. 512 threads:
//   g = tid>>6 (8-way i-split, 32 cand rows each), b = tid&63.
//   Each thread accumulates BOTH jl outputs; every cand value loaded exactly
//   once per CTA, straight from L2 (front-batched LDG, MLP=32).
__global__ __launch_bounds__(512, 1)
void rnn_kernel(const int* __restrict__ input_len,
                const float* __restrict__ bi, const float* __restrict__ bhb,
                const float* __restrict__ Wh) {
    __shared__ float s_Wp[256 * 8];     // [i][jl][nh]  8 KB
    __shared__ float s_y[8 * 128 * 4];  // [g][jl*64+b][nh]  16 KB

    const int tid = threadIdx.x, cid = blockIdx.x;
    const int g = tid >> 6, b = tid & 63;
    const int jl = (tid >> 6) & 1;          // valid for tail threads (tid<128)
    const int j = cid * 2 + jl;

    // pack Wh: s_Wp[i*8 + jl*4 + nh] = Wh[2c+jl][nh*256 + i]
    for (int u = tid; u < 2048; u += 512) {
        int i = u >> 3, ujl = (u >> 2) & 1, nh = u & 3;
        s_Wp[u] = Wh[(size_t)(cid * 2 + ujl) * NHH + nh * H + i];
    }

    float bsum = 0.f, myc = 0.f;
    int mylen = 0;
    if (tid < 128) {
        bsum = bi[j] + bhb[j];
        mylen = input_len[b];
        // cand(0) = tanh(P[0] + bias)   (z = 0)
        myc = tanhf(g_P[(size_t)j * B + b] + bsum);
        __stcg(&g_cand[0][j * B + b], myc);
    }
    float z0 = 0.f, z1 = 0.f, z2 = 0.f, z3 = 0.f;
    float h0 = 0.f, h1 = 0.f, h2 = 0.f, h3 = 0.f;
    unsigned bcnt = 0;

    grid_barrier(bcnt, tid, cid);        // also covers s_Wp staging

    #pragma unroll 1
    for (int t = 0; t < S; ++t) {
        const int p = t & 1;
        const float* cand = g_cand[p];

        // front-batched cand loads: 32 independent LDGs in flight
        float cv[32];
        {
            const float* cb = cand + (g << 5) * B + b;
            #pragma unroll
            for (int k = 0; k < 32; ++k) cv[k] = __ldcg(cb + k * B);
        }

        // tail-thread prefetches (issued behind the cand batch)
        float pnext = 0.0f;
        float4 g4 = make_float4(0.f, 0.f, 0.f, 0.f);
        if (tid < 128) {
            if (t < S - 1)
                pnext = g_P[(size_t)(t + 1) * (H * B) + (size_t)j * B + b];
            g4 = *(const float4*)&g_gate[(size_t)t * (B * NH) + b * 4];
        }

        // partial y over our 32 cand rows, both jl at once
        float a0 = 0.f, a1 = 0.f, a2 = 0.f, a3 = 0.f;   // jl = 0
        float c0 = 0.f, c1 = 0.f, c2 = 0.f, c3 = 0.f;   // jl = 1
        const float4* wb = (const float4*)&s_Wp[(g << 5) * 8];
        #pragma unroll
        for (int k = 0; k < 32; ++k) {
            float4 wA = wb[k * 2];          // warp-broadcast LDS.128
            float4 wB = wb[k * 2 + 1];
            a0 = fmaf(wA.x, cv[k], a0); a1 = fmaf(wA.y, cv[k], a1);
            a2 = fmaf(wA.z, cv[k], a2); a3 = fmaf(wA.w, cv[k], a3);
            c0 = fmaf(wB.x, cv[k], c0); c1 = fmaf(wB.y, cv[k], c1);
            c2 = fmaf(wB.z, cv[k], c2); c3 = fmaf(wB.w, cv[k], c3);
        }
        *(float4*)&s_y[(g * 128 + b) * 4]      = make_float4(a0, a1, a2, a3);
        *(float4*)&s_y[(g * 128 + 64 + b) * 4] = make_float4(c0, c1, c2, c3);
        __syncthreads();

        if (tid < 128) {
            float y0 = 0.f, y1 = 0.f, y2 = 0.f, y3 = 0.f;
            #pragma unroll
            for (int gg = 0; gg < 8; ++gg) {
                float4 yv = *(const float4*)&s_y[(gg * 128 + jl * 64 + b) * 4];
                y0 += yv.x; y1 += yv.y; y2 += yv.z; y3 += yv.w;
            }
            z0 = fmaf(g4.x, y0 - z0, z0);        // z' = z + g*(y - z)
            z1 = fmaf(g4.y, y1 - z1, z1);
            z2 = fmaf(g4.z, y2 - z2, z2);
            z3 = fmaf(g4.w, y3 - z3, z3);
            h0 = fmaf(g4.x, myc - h0, h0);       // h' = h + g*(cand - h)
            h1 = fmaf(g4.y, myc - h1, h1);
            h2 = fmaf(g4.z, myc - h2, h2);
            h3 = fmaf(g4.w, myc - h3, h3);

            if (t == mylen - 1) {
                g_sel[b * NHH + 0 * H + j] = h0;
                g_sel[b * NHH + 1 * H + j] = h1;
                g_sel[b * NHH + 2 * H + j] = h2;
                g_sel[b * NHH + 3 * H + j] = h3;
            }
            if (t < S - 1) {
                myc = tanhf(pnext + bsum + z0 + z1 + z2 + z3);
                __stcg(&g_cand[p ^ 1][j * B + b], myc);
            }
        }
        grid_barrier(bcnt, tid, cid);
    }
}

// ---------------- readout ---------------------------------------------------
__global__ __launch_bounds__(256)
void final_fc_kernel(const float* __restrict__ fc1_W,
                     const float* __restrict__ fc1_b,
                     const float* __restrict__ fc2_W,
                     const float* __restrict__ fc2_b,
                     float* __restrict__ out) {
    __shared__ float selsh[NHH];
    __shared__ float red0[H];
    __shared__ float red1[H];
    const int b = blockIdx.x;
    const int j = threadIdx.x;

    #pragma unroll
    for (int i = 0; i < NH; ++i)
        selsh[i * H + j] = g_sel[b * NHH + i * H + j];
    __syncthreads();

    float s = fc1_b[j];
    const float4* w = (const float4*)(fc1_W + (size_t)j * NHH);
    #pragma unroll 4
    for (int k4 = 0; k4 < NHH / 4; ++k4) {
        float4 wv = w[k4];
        float4 sv = *(const float4*)&selsh[k4 * 4];
        s = fmaf(wv.x, sv.x, s);
        s = fmaf(wv.y, sv.y, s);
        s = fmaf(wv.z, sv.z, s);
        s = fmaf(wv.w, sv.w, s);
    }
    s = tanhf(s);
    red0[j] = s * fc2_W[j];
    red1[j] = s * fc2_W[H + j];
    __syncthreads();

    for (int stride = 128; stride >= 1; stride >>= 1) {
        if (j < stride) {
            red0[j] += red0[j + stride];
            red1[j] += red1[j + stride];
        }
        __syncthreads();
    }
    if (j == 0) {
        out[b * 2 + 0] = red0[0] + fc2_b[0];
        out[b * 2 + 1] = red1[0] + fc2_b[1];
    }
}

// ---------------------------------------------------------------------------
extern "C" void kernel_launch(void* const* d_in, const int* in_sizes, int n_in,
                              void* d_out, int out_size) {
    const int*   src       = (const int*)  d_in[0];
    const int*   input_len = (const int*)  d_in[1];
    const float* fix_src   = (const float*)d_in[2];
    const float* emb_table = (const float*)d_in[3];
    const float* Wi        = (const float*)d_in[4];
    const float* bi        = (const float*)d_in[5];
    const float* Wh        = (const float*)d_in[6];
    const float* bh        = (const float*)d_in[7];
    const float* fc1_W     = (const float*)d_in[8];
    const float* fc1_b     = (const float*)d_in[9];
    const float* fc2_W     = (const float*)d_in[10];
    const float* fc2_b     = (const float*)d_in[11];
    float* out = (float*)d_out;

    init_kernel<<<1, 128>>>();
    gate_kernel<<<S, 256>>>(fix_src);
    p_kernel<<<2 * S, 256>>>(src, emb_table, Wi);
    rnn_kernel<<<NCTA, 512>>>(input_len, bi, bh, Wh);
    final_fc_kernel<<<B, 256>>>(fc1_W, fc1_b, fc2_W, fc2_b, out);
}

// round 9
// speedup vs baseline: 2.6247x; 2.6247x over previous
#include <cuda_runtime.h>
#include <math.h>

#define S   512
#define B   64
#define H   256
#define NH  4
#define NHH 1024      // NH*H
#define NCTA 128

// ---------------- device globals (no runtime allocation allowed) ------------
__device__ float g_P[(size_t)S * H * B];       // [t][j][b]  : x@Wi.T
__device__ float g_gate[(size_t)S * B * NH];   // [t][b][nh] : sigmoid gates
__device__ float g_cand[2][H * B];             // double-buffered cand, [j][b]
__device__ float g_sel[B * NHH];               // hcat at t = len-1
__device__ __align__(128) unsigned g_count;    // barrier arrival counter
__device__ __align__(128) unsigned g_epoch;    // barrier release epoch

// ---------------- init: reset barrier state each replay ---------------------
__global__ void init_kernel() {
    if (threadIdx.x == 0) { g_count = 0u; g_epoch = 0u; }
}

// ---------------- gate precompute: g = sigmoid(d - 3*nh) --------------------
__global__ __launch_bounds__(256)
void gate_kernel(const float* __restrict__ fix_src) {
    int t = blockIdx.x;
    int tid = threadIdx.x;          // b = tid>>2, nh = tid&3
    int b = tid >> 2, nh = tid & 3;
    float d = fix_src[b * S + t];
    g_gate[(size_t)t * (B * NH) + tid] = 1.0f / (1.0f + expf(3.0f * (float)nh - d));
}

// ---------------- P precompute: P[t][j][b] = emb[src[b,t]] . Wi[j,:] --------
__global__ __launch_bounds__(256, 2)
void p_kernel(const int* __restrict__ src, const float* __restrict__ emb,
              const float* __restrict__ Wi) {
    __shared__ float s_x[32][256];
    __shared__ int s_tok[32];
    const int t = blockIdx.x >> 1, bh = blockIdx.x & 1;
    const int tid = threadIdx.x;

    if (tid < 32) s_tok[tid] = src[(bh * 32 + tid) * S + t];
    __syncthreads();
    {
        int row = tid >> 3, seg = tid & 7;
        const float4* sp = (const float4*)(emb + (size_t)s_tok[row] * H) + seg * 8;
        float4* dp = (float4*)(&s_x[row][0]) + seg * 8;
        #pragma unroll
        for (int q = 0; q < 8; ++q) dp[q] = sp[q];
    }
    __syncthreads();

    float acc[32];
    #pragma unroll
    for (int m = 0; m < 32; ++m) acc[m] = 0.0f;
    const int j = tid;
    const float4* w4p = (const float4*)(Wi + (size_t)j * H);

    #pragma unroll 2
    for (int k4 = 0; k4 < 64; ++k4) {
        float4 wv = w4p[k4];
        #pragma unroll
        for (int m = 0; m < 32; ++m) {
            float4 xv = *(const float4*)&s_x[m][k4 * 4];
            acc[m] = fmaf(wv.x, xv.x, acc[m]);
            acc[m] = fmaf(wv.y, xv.y, acc[m]);
            acc[m] = fmaf(wv.z, xv.z, acc[m]);
            acc[m] = fmaf(wv.w, xv.w, acc[m]);
        }
    }
    float* out = g_P + (size_t)t * (H * B) + (size_t)j * B + bh * 32;
    #pragma unroll
    for (int m4 = 0; m4 < 8; ++m4)
        ((float4*)out)[m4] = make_float4(acc[m4 * 4], acc[m4 * 4 + 1],
                                         acc[m4 * 4 + 2], acc[m4 * 4 + 3]);
}

// ---------------- central-counter grid barrier (1 poller/CTA) ---------------
// Proven in R6 (2084 us). Do not replace with multi-threaded volatile polls.
__device__ __forceinline__ void grid_barrier(unsigned& bcnt, int tid) {
    __syncthreads();                      // CTA arrival; cta-scope hb to tid0
    ++bcnt;
    if (tid == 0) {
        unsigned ret;
        asm volatile("atom.release.gpu.global.add.u32 %0, [%1], 1;"
                     : "=r"(ret) : "l"(&g_count) : "memory");
        if (ret == bcnt * NCTA - 1)       // last arriver of this phase
            asm volatile("st.release.gpu.global.u32 [%0], %1;"
                         :: "l"(&g_epoch), "r"(bcnt) : "memory");
        unsigned e;
        do {
            asm volatile("ld.acquire.gpu.global.u32 %0, [%1];"
                         : "=r"(e) : "l"(&g_epoch) : "memory");
        } while (e < bcnt);
    }
    __syncthreads();                      // release CTA; hb from tid0 acquire
}

// ---------------- persistent recurrent kernel -------------------------------
// 128 CTAs, CTA c owns output columns j = {2c, 2c+1}. 512 threads:
//   g = tid>>6 (8-way i-split, 32 cand rows each), b = tid&63.
//   Each thread accumulates BOTH jl outputs; every cand value loaded exactly
//   once per CTA, straight from L2 (front-batched LDG, MLP=32).
__global__ __launch_bounds__(512, 1)
void rnn_kernel(const int* __restrict__ input_len,
                const float* __restrict__ bi, const float* __restrict__ bhb,
                const float* __restrict__ Wh) {
    __shared__ float s_Wp[256 * 8];     // [i][jl][nh]  8 KB
    __shared__ float s_y[8 * 128 * 4];  // [g][jl*64+b][nh]  16 KB

    const int tid = threadIdx.x, cid = blockIdx.x;
    const int g = tid >> 6, b = tid & 63;
    const int jl = (tid >> 6) & 1;          // valid for tail threads (tid<128)
    const int j = cid * 2 + jl;

    // pack Wh: s_Wp[i*8 + jl*4 + nh] = Wh[2c+jl][nh*256 + i]
    for (int u = tid; u < 2048; u += 512) {
        int i = u >> 3, ujl = (u >> 2) & 1, nh = u & 3;
        s_Wp[u] = Wh[(size_t)(cid * 2 + ujl) * NHH + nh * H + i];
    }

    float bsum = 0.f, myc = 0.f;
    int mylen = 0;
    if (tid < 128) {
        bsum = bi[j] + bhb[j];
        mylen = input_len[b];
        // cand(0) = tanh(P[0] + bias)   (z = 0)
        myc = tanhf(g_P[(size_t)j * B + b] + bsum);
        __stcg(&g_cand[0][j * B + b], myc);
    }
    float z0 = 0.f, z1 = 0.f, z2 = 0.f, z3 = 0.f;
    float h0 = 0.f, h1 = 0.f, h2 = 0.f, h3 = 0.f;
    unsigned bcnt = 0;

    grid_barrier(bcnt, tid);             // also covers s_Wp staging

    #pragma unroll 1
    for (int t = 0; t < S; ++t) {
        const int p = t & 1;
        const float* cand = g_cand[p];

        // front-batched cand loads: 32 independent LDGs in flight
        float cv[32];
        {
            const float* cb = cand + (g << 5) * B + b;
            #pragma unroll
            for (int k = 0; k < 32; ++k) cv[k] = __ldcg(cb + k * B);
        }

        // tail-thread prefetches (issued behind the cand batch)
        float pnext = 0.0f;
        float4 g4 = make_float4(0.f, 0.f, 0.f, 0.f);
        if (tid < 128) {
            if (t < S - 1)
                pnext = g_P[(size_t)(t + 1) * (H * B) + (size_t)j * B + b];
            g4 = *(const float4*)&g_gate[(size_t)t * (B * NH) + b * 4];
        }

        // partial y over our 32 cand rows, both jl at once
        float a0 = 0.f, a1 = 0.f, a2 = 0.f, a3 = 0.f;   // jl = 0
        float c0 = 0.f, c1 = 0.f, c2 = 0.f, c3 = 0.f;   // jl = 1
        const float4* wb = (const float4*)&s_Wp[(g << 5) * 8];
        #pragma unroll
        for (int k = 0; k < 32; ++k) {
            float4 wA = wb[k * 2];          // warp-broadcast LDS.128
            float4 wB = wb[k * 2 + 1];
            a0 = fmaf(wA.x, cv[k], a0); a1 = fmaf(wA.y, cv[k], a1);
            a2 = fmaf(wA.z, cv[k], a2); a3 = fmaf(wA.w, cv[k], a3);
            c0 = fmaf(wB.x, cv[k], c0); c1 = fmaf(wB.y, cv[k], c1);
            c2 = fmaf(wB.z, cv[k], c2); c3 = fmaf(wB.w, cv[k], c3);
        }
        *(float4*)&s_y[(g * 128 + b) * 4]      = make_float4(a0, a1, a2, a3);
        *(float4*)&s_y[(g * 128 + 64 + b) * 4] = make_float4(c0, c1, c2, c3);
        __syncthreads();

        if (tid < 128) {
            float y0 = 0.f, y1 = 0.f, y2 = 0.f, y3 = 0.f;
            #pragma unroll
            for (int gg = 0; gg < 8; ++gg) {
                float4 yv = *(const float4*)&s_y[(gg * 128 + jl * 64 + b) * 4];
                y0 += yv.x; y1 += yv.y; y2 += yv.z; y3 += yv.w;
            }
            z0 = fmaf(g4.x, y0 - z0, z0);        // z' = z + g*(y - z)
            z1 = fmaf(g4.y, y1 - z1, z1);
            z2 = fmaf(g4.z, y2 - z2, z2);
            z3 = fmaf(g4.w, y3 - z3, z3);
            h0 = fmaf(g4.x, myc - h0, h0);       // h' = h + g*(cand - h)
            h1 = fmaf(g4.y, myc - h1, h1);
            h2 = fmaf(g4.z, myc - h2, h2);
            h3 = fmaf(g4.w, myc - h3, h3);

            if (t == mylen - 1) {
                g_sel[b * NHH + 0 * H + j] = h0;
                g_sel[b * NHH + 1 * H + j] = h1;
                g_sel[b * NHH + 2 * H + j] = h2;
                g_sel[b * NHH + 3 * H + j] = h3;
            }
            if (t < S - 1) {
                myc = tanhf(pnext + bsum + z0 + z1 + z2 + z3);
                __stcg(&g_cand[p ^ 1][j * B + b], myc);
            }
        }
        grid_barrier(bcnt, tid);
    }
}

// ---------------- readout ---------------------------------------------------
__global__ __launch_bounds__(256)
void final_fc_kernel(const float* __restrict__ fc1_W,
                     const float* __restrict__ fc1_b,
                     const float* __restrict__ fc2_W,
                     const float* __restrict__ fc2_b,
                     float* __restrict__ out) {
    __shared__ float selsh[NHH];
    __shared__ float red0[H];
    __shared__ float red1[H];
    const int b = blockIdx.x;
    const int j = threadIdx.x;

    #pragma unroll
    for (int i = 0; i < NH; ++i)
        selsh[i * H + j] = g_sel[b * NHH + i * H + j];
    __syncthreads();

    float s = fc1_b[j];
    const float4* w = (const float4*)(fc1_W + (size_t)j * NHH);
    #pragma unroll 4
    for (int k4 = 0; k4 < NHH / 4; ++k4) {
        float4 wv = w[k4];
        float4 sv = *(const float4*)&selsh[k4 * 4];
        s = fmaf(wv.x, sv.x, s);
        s = fmaf(wv.y, sv.y, s);
        s = fmaf(wv.z, sv.z, s);
        s = fmaf(wv.w, sv.w, s);
    }
    s = tanhf(s);
    red0[j] = s * fc2_W[j];
    red1[j] = s * fc2_W[H + j];
    __syncthreads();

    for (int stride = 128; stride >= 1; stride >>= 1) {
        if (j < stride) {
            red0[j] += red0[j + stride];
            red1[j] += red1[j + stride];
        }
        __syncthreads();
    }
    if (j == 0) {
        out[b * 2 + 0] = red0[0] + fc2_b[0];
        out[b * 2 + 1] = red1[0] + fc2_b[1];
    }
}

// ---------------------------------------------------------------------------
extern "C" void kernel_launch(void* const* d_in, const int* in_sizes, int n_in,
                              void* d_out, int out_size) {
    const int*   src       = (const int*)  d_in[0];
    const int*   input_len = (const int*)  d_in[1];
    const float* fix_src   = (const float*)d_in[2];
    const float* emb_table = (const float*)d_in[3];
    const float* Wi        = (const float*)d_in[4];
    const float* bi        = (const float*)d_in[5];
    const float* Wh        = (const float*)d_in[6];
    const float* bh        = (const float*)d_in[7];
    const float* fc1_W     = (const float*)d_in[8];
    const float* fc1_b     = (const float*)d_in[9];
    const float* fc2_W     = (const float*)d_in[10];
    const float* fc2_b     = (const float*)d_in[11];
    float* out = (float*)d_out;

    init_kernel<<<1, 32>>>();
    gate_kernel<<<S, 256>>>(fix_src);
    p_kernel<<<2 * S, 256>>>(src, emb_table, Wi);
    rnn_kernel<<<NCTA, 512>>>(input_len, bi, bh, Wh);
    final_fc_kernel<<<B, 256>>>(fc1_W, fc1_b, fc2_W, fc2_b, out);
}

// round 10
// speedup vs baseline: 2.7327x; 1.0411x over previous
#include <cuda_runtime.h>
#include <math.h>

#define S   512
#define B   64
#define H   256
#define NH  4
#define NHH 1024      // NH*H
#define NCTA 128

// ---------------- device globals (no runtime allocation allowed) ------------
__device__ float g_P[(size_t)S * H * B];       // [t][j][b]  : x@Wi.T
__device__ float g_gate[(size_t)S * B * NH];   // [t][b][nh] : sigmoid gates
__device__ float g_cand[2][H * B];             // double-buffered cand, [j][b]
__device__ float g_sel[B * NHH];               // hcat at t = len-1
__device__ __align__(128) unsigned g_count[64];  // [team*32] arrival counters
__device__ __align__(128) unsigned g_epoch[64];  // [team*32] release epochs

// ---------------- init: reset barrier state each replay ---------------------
__global__ void init_kernel() {
    int i = threadIdx.x;
    if (i < 64) { g_count[i] = 0u; g_epoch[i] = 0u; }
}

// ---------------- gate precompute: g = sigmoid(d - 3*nh) --------------------
__global__ __launch_bounds__(256)
void gate_kernel(const float* __restrict__ fix_src) {
    int t = blockIdx.x;
    int tid = threadIdx.x;          // b = tid>>2, nh = tid&3
    int b = tid >> 2, nh = tid & 3;
    float d = fix_src[b * S + t];
    g_gate[(size_t)t * (B * NH) + tid] = 1.0f / (1.0f + expf(3.0f * (float)nh - d));
}

// ---------------- P precompute: P[t][j][b] = emb[src[b,t]] . Wi[j,:] --------
__global__ __launch_bounds__(256, 2)
void p_kernel(const int* __restrict__ src, const float* __restrict__ emb,
              const float* __restrict__ Wi) {
    __shared__ float s_x[32][256];
    __shared__ int s_tok[32];
    const int t = blockIdx.x >> 1, bh = blockIdx.x & 1;
    const int tid = threadIdx.x;

    if (tid < 32) s_tok[tid] = src[(bh * 32 + tid) * S + t];
    __syncthreads();
    {
        int row = tid >> 3, seg = tid & 7;
        const float4* sp = (const float4*)(emb + (size_t)s_tok[row] * H) + seg * 8;
        float4* dp = (float4*)(&s_x[row][0]) + seg * 8;
        #pragma unroll
        for (int q = 0; q < 8; ++q) dp[q] = sp[q];
    }
    __syncthreads();

    float acc[32];
    #pragma unroll
    for (int m = 0; m < 32; ++m) acc[m] = 0.0f;
    const int j = tid;
    const float4* w4p = (const float4*)(Wi + (size_t)j * H);

    #pragma unroll 2
    for (int k4 = 0; k4 < 64; ++k4) {
        float4 wv = w4p[k4];
        #pragma unroll
        for (int m = 0; m < 32; ++m) {
            float4 xv = *(const float4*)&s_x[m][k4 * 4];
            acc[m] = fmaf(wv.x, xv.x, acc[m]);
            acc[m] = fmaf(wv.y, xv.y, acc[m]);
            acc[m] = fmaf(wv.z, xv.z, acc[m]);
            acc[m] = fmaf(wv.w, xv.w, acc[m]);
        }
    }
    float* out = g_P + (size_t)t * (H * B) + (size_t)j * B + bh * 32;
    #pragma unroll
    for (int m4 = 0; m4 < 8; ++m4)
        ((float4*)out)[m4] = make_float4(acc[m4 * 4], acc[m4 * 4 + 1],
                                         acc[m4 * 4 + 2], acc[m4 * 4 + 3]);
}

// ---------------- per-team named barrier ------------------------------------
__device__ __forceinline__ void team_bar(int team) {
    asm volatile("bar.sync %0, 256;" :: "r"(team + 1) : "memory");
}

// ---------------- per-team central-counter grid barrier ---------------------
// Same proven R6 structure, one instance per team (separate cache lines).
__device__ __forceinline__ void team_grid_barrier(unsigned& bcnt, int tt, int team) {
    team_bar(team);                       // team arrival; cta-scope hb to tt0
    ++bcnt;
    if (tt == 0) {
        unsigned* cnt = &g_count[team << 5];
        unsigned* ep  = &g_epoch[team << 5];
        unsigned ret;
        asm volatile("atom.release.gpu.global.add.u32 %0, [%1], 1;"
                     : "=r"(ret) : "l"(cnt) : "memory");
        if (ret == bcnt * NCTA - 1)       // last arriver of this phase
            asm volatile("st.release.gpu.global.u32 [%0], %1;"
                         :: "l"(ep), "r"(bcnt) : "memory");
        unsigned e;
        do {
            asm volatile("ld.acquire.gpu.global.u32 %0, [%1];"
                         : "=r"(e) : "l"(ep) : "memory");
        } while (e < bcnt);
    }
    team_bar(team);                       // release team; hb from tt0 acquire
}

// ---------------- persistent recurrent kernel -------------------------------
// 128 CTAs, CTA c owns output columns j = {2c, 2c+1}. 512 threads split into
// two INDEPENDENT teams (batch halves) with separate grid barriers:
//   team = tid>>8 : b in [team*32, team*32+32)
//   tt = tid&255, g = tt>>5 (8-way i-split, 32 rows), bb = tt&31.
// While one team waits on its grid barrier, the other team's warps compute.
__global__ __launch_bounds__(512, 1)
void rnn_kernel(const int* __restrict__ input_len,
                const float* __restrict__ bi, const float* __restrict__ bhb,
                const float* __restrict__ Wh) {
    __shared__ float s_Wp[256 * 8];        // [i][jl][nh]  8 KB (shared, RO)
    __shared__ float s_y[2][8][64][4];     // [team][g][jl*32+bb][nh]  16 KB

    const int tid = threadIdx.x, cid = blockIdx.x;
    const int team = tid >> 8, tt = tid & 255;
    const int g = tt >> 5, bb = tt & 31;
    const int b = (team << 5) + bb;        // global batch index
    const int tjl = tt >> 5;               // tail threads (tt<64): jl
    const int j = cid * 2 + tjl;

    // pack Wh: s_Wp[i*8 + jl*4 + nh] = Wh[2c+jl][nh*256 + i]
    for (int u = tid; u < 2048; u += 512) {
        int i = u >> 3, ujl = (u >> 2) & 1, nh = u & 3;
        s_Wp[u] = Wh[(size_t)(cid * 2 + ujl) * NHH + nh * H + i];
    }
    __syncthreads();                       // s_Wp visible to both teams

    float bsum = 0.f, myc = 0.f;
    int mylen = 0;
    if (tt < 64) {                         // team tail: (jl, bb) pairs
        bsum = bi[j] + bhb[j];
        mylen = input_len[b];
        // cand(0) = tanh(P[0] + bias)   (z = 0)
        myc = tanhf(g_P[(size_t)j * B + b] + bsum);
        __stcg(&g_cand[0][j * B + b], myc);
    }
    float z0 = 0.f, z1 = 0.f, z2 = 0.f, z3 = 0.f;
    float h0 = 0.f, h1 = 0.f, h2 = 0.f, h3 = 0.f;
    unsigned bcnt = 0;

    team_grid_barrier(bcnt, tt, team);     // covers cand(0) of this team

    #pragma unroll 1
    for (int t = 0; t < S; ++t) {
        const int p = t & 1;
        const float* cand = g_cand[p];

        // tail-thread prefetches
        float pnext = 0.0f;
        float4 g4 = make_float4(0.f, 0.f, 0.f, 0.f);
        if (tt < 64) {
            if (t < S - 1)
                pnext = g_P[(size_t)(t + 1) * (H * B) + (size_t)j * B + b];
            g4 = *(const float4*)&g_gate[(size_t)t * (B * NH) + b * 4];
        }

        // partial y over our 32 cand rows, both jl at once (R6-proven loop)
        float a0 = 0.f, a1 = 0.f, a2 = 0.f, a3 = 0.f;   // jl = 0
        float c0 = 0.f, c1 = 0.f, c2 = 0.f, c3 = 0.f;   // jl = 1
        const float* cb = cand + (g << 5) * B + b;
        const float4* wb = (const float4*)&s_Wp[(g << 5) * 8];
        #pragma unroll 8
        for (int k = 0; k < 32; ++k) {
            float cv = __ldcg(cb + k * B);
            float4 wA = wb[k * 2];          // warp-broadcast LDS.128
            float4 wB = wb[k * 2 + 1];
            a0 = fmaf(wA.x, cv, a0); a1 = fmaf(wA.y, cv, a1);
            a2 = fmaf(wA.z, cv, a2); a3 = fmaf(wA.w, cv, a3);
            c0 = fmaf(wB.x, cv, c0); c1 = fmaf(wB.y, cv, c1);
            c2 = fmaf(wB.z, cv, c2); c3 = fmaf(wB.w, cv, c3);
        }
        *(float4*)&s_y[team][g][bb][0]      = make_float4(a0, a1, a2, a3);
        *(float4*)&s_y[team][g][32 + bb][0] = make_float4(c0, c1, c2, c3);
        team_bar(team);                     // partials visible within team

        if (tt < 64) {
            float y0 = 0.f, y1 = 0.f, y2 = 0.f, y3 = 0.f;
            #pragma unroll
            for (int gg = 0; gg < 8; ++gg) {
                float4 yv = *(const float4*)&s_y[team][gg][tjl * 32 + bb][0];
                y0 += yv.x; y1 += yv.y; y2 += yv.z; y3 += yv.w;
            }
            z0 = fmaf(g4.x, y0 - z0, z0);        // z' = z + g*(y - z)
            z1 = fmaf(g4.y, y1 - z1, z1);
            z2 = fmaf(g4.z, y2 - z2, z2);
            z3 = fmaf(g4.w, y3 - z3, z3);
            h0 = fmaf(g4.x, myc - h0, h0);       // h' = h + g*(cand - h)
            h1 = fmaf(g4.y, myc - h1, h1);
            h2 = fmaf(g4.z, myc - h2, h2);
            h3 = fmaf(g4.w, myc - h3, h3);

            if (t == mylen - 1) {
                g_sel[b * NHH + 0 * H + j] = h0;
                g_sel[b * NHH + 1 * H + j] = h1;
                g_sel[b * NHH + 2 * H + j] = h2;
                g_sel[b * NHH + 3 * H + j] = h3;
            }
            if (t < S - 1) {
                myc = tanhf(pnext + bsum + z0 + z1 + z2 + z3);
                __stcg(&g_cand[p ^ 1][j * B + b], myc);
            }
        }
        team_grid_barrier(bcnt, tt, team);
    }
}

// ---------------- readout ---------------------------------------------------
__global__ __launch_bounds__(256)
void final_fc_kernel(const float* __restrict__ fc1_W,
                     const float* __restrict__ fc1_b,
                     const float* __restrict__ fc2_W,
                     const float* __restrict__ fc2_b,
                     float* __restrict__ out) {
    __shared__ float selsh[NHH];
    __shared__ float red0[H];
    __shared__ float red1[H];
    const int b = blockIdx.x;
    const int j = threadIdx.x;

    #pragma unroll
    for (int i = 0; i < NH; ++i)
        selsh[i * H + j] = g_sel[b * NHH + i * H + j];
    __syncthreads();

    float s = fc1_b[j];
    const float4* w = (const float4*)(fc1_W + (size_t)j * NHH);
    #pragma unroll 4
    for (int k4 = 0; k4 < NHH / 4; ++k4) {
        float4 wv = w[k4];
        float4 sv = *(const float4*)&selsh[k4 * 4];
        s = fmaf(wv.x, sv.x, s);
        s = fmaf(wv.y, sv.y, s);
        s = fmaf(wv.z, sv.z, s);
        s = fmaf(wv.w, sv.w, s);
    }
    s = tanhf(s);
    red0[j] = s * fc2_W[j];
    red1[j] = s * fc2_W[H + j];
    __syncthreads();

    for (int stride = 128; stride >= 1; stride >>= 1) {
        if (j < stride) {
            red0[j] += red0[j + stride];
            red1[j] += red1[j + stride];
        }
        __syncthreads();
    }
    if (j == 0) {
        out[b * 2 + 0] = red0[0] + fc2_b[0];
        out[b * 2 + 1] = red1[0] + fc2_b[1];
    }
}

// ---------------------------------------------------------------------------
extern "C" void kernel_launch(void* const* d_in, const int* in_sizes, int n_in,
                              void* d_out, int out_size) {
    const int*   src       = (const int*)  d_in[0];
    const int*   input_len = (const int*)  d_in[1];
    const float* fix_src   = (const float*)d_in[2];
    const float* emb_table = (const float*)d_in[3];
    const float* Wi        = (const float*)d_in[4];
    const float* bi        = (const float*)d_in[5];
    const float* Wh        = (const float*)d_in[6];
    const float* bh        = (const float*)d_in[7];
    const float* fc1_W     = (const float*)d_in[8];
    const float* fc1_b     = (const float*)d_in[9];
    const float* fc2_W     = (const float*)d_in[10];
    const float* fc2_b     = (const float*)d_in[11];
    float* out = (float*)d_out;

    init_kernel<<<1, 64>>>();
    gate_kernel<<<S, 256>>>(fix_src);
    p_kernel<<<2 * S, 256>>>(src, emb_table, Wi);
    rnn_kernel<<<NCTA, 512>>>(input_len, bi, bh, Wh);
    final_fc_kernel<<<B, 256>>>(fc1_W, fc1_b, fc2_W, fc2_b, out);
}

// round 11
// speedup vs baseline: 2.7847x; 1.0190x over previous
#include <cuda_runtime.h>
#include <math.h>

#define S   512
#define B   64
#define H   256
#define NH  4
#define NHH 1024      // NH*H
#define NCTA 128

// ---------------- device globals (no runtime allocation allowed) ------------
__device__ float g_P[(size_t)S * H * B];       // [t][j][b]  : x@Wi.T
__device__ float g_gate[(size_t)S * B * NH];   // [t][b][nh] : sigmoid gates
// cand, ping-pong, packed {tag(hi32)=t, value(lo32)} per (j,b). Single 8B
// store/load is atomic -> tag rides with data, no fences needed.
__device__ unsigned long long g_cand[2][H * B];
__device__ float g_sel[B * NHH];               // hcat at t = len-1

// ---------------- init: reset cand tags to sentinel each replay -------------
__global__ void init_kernel() {
    int i = blockIdx.x * blockDim.x + threadIdx.x;      // 0 .. 16383
    const unsigned long long sent = 0xFFFFFFFF00000000ULL;
    g_cand[0][i] = sent;
    g_cand[1][i] = sent;
}

// ---------------- gate precompute: g = sigmoid(d - 3*nh) --------------------
__global__ __launch_bounds__(256)
void gate_kernel(const float* __restrict__ fix_src) {
    int t = blockIdx.x;
    int tid = threadIdx.x;          // b = tid>>2, nh = tid&3
    int b = tid >> 2, nh = tid & 3;
    float d = fix_src[b * S + t];
    g_gate[(size_t)t * (B * NH) + tid] = 1.0f / (1.0f + expf(3.0f * (float)nh - d));
}

// ---------------- P precompute: P[t][j][b] = emb[src[b,t]] . Wi[j,:] --------
__global__ __launch_bounds__(256, 2)
void p_kernel(const int* __restrict__ src, const float* __restrict__ emb,
              const float* __restrict__ Wi) {
    __shared__ float s_x[32][256];
    __shared__ int s_tok[32];
    const int t = blockIdx.x >> 1, bh = blockIdx.x & 1;
    const int tid = threadIdx.x;

    if (tid < 32) s_tok[tid] = src[(bh * 32 + tid) * S + t];
    __syncthreads();
    {
        int row = tid >> 3, seg = tid & 7;
        const float4* sp = (const float4*)(emb + (size_t)s_tok[row] * H) + seg * 8;
        float4* dp = (float4*)(&s_x[row][0]) + seg * 8;
        #pragma unroll
        for (int q = 0; q < 8; ++q) dp[q] = sp[q];
    }
    __syncthreads();

    float acc[32];
    #pragma unroll
    for (int m = 0; m < 32; ++m) acc[m] = 0.0f;
    const int j = tid;
    const float4* w4p = (const float4*)(Wi + (size_t)j * H);

    #pragma unroll 2
    for (int k4 = 0; k4 < 64; ++k4) {
        float4 wv = w4p[k4];
        #pragma unroll
        for (int m = 0; m < 32; ++m) {
            float4 xv = *(const float4*)&s_x[m][k4 * 4];
            acc[m] = fmaf(wv.x, xv.x, acc[m]);
            acc[m] = fmaf(wv.y, xv.y, acc[m]);
            acc[m] = fmaf(wv.z, xv.z, acc[m]);
            acc[m] = fmaf(wv.w, xv.w, acc[m]);
        }
    }
    float* out = g_P + (size_t)t * (H * B) + (size_t)j * B + bh * 32;
    #pragma unroll
    for (int m4 = 0; m4 < 8; ++m4)
        ((float4*)out)[m4] = make_float4(acc[m4 * 4], acc[m4 * 4 + 1],
                                         acc[m4 * 4 + 2], acc[m4 * 4 + 3]);
}

// ---------------- persistent recurrent kernel: dataflow sync, NO barrier ----
// 128 CTAs, CTA c owns output columns j = {2c, 2c+1}. 512 threads:
//   g = tid>>6 (8-way i-split, 32 cand rows each), b = tid&63.
//   Each thread accumulates BOTH jl outputs (8 accumulators).
// Cross-CTA sync is the tag in each 8B cand word; CTAs skew <= 2 steps.
__global__ __launch_bounds__(512, 1)
void rnn_kernel(const int* __restrict__ input_len,
                const float* __restrict__ bi, const float* __restrict__ bhb,
                const float* __restrict__ Wh) {
    __shared__ float s_Wp[256 * 8];        // [i][jl][nh]  8 KB
    __shared__ float s_y[2][8][128][4];    // parity-buffered partials, 32 KB

    const int tid = threadIdx.x, cid = blockIdx.x;
    const int g = tid >> 6, b = tid & 63;
    const int jl = (tid >> 6) & 1;         // valid for tail threads (tid<128)
    const int j = cid * 2 + jl;

    // pack Wh: s_Wp[i*8 + jl*4 + nh] = Wh[2c+jl][nh*256 + i]
    for (int u = tid; u < 2048; u += 512) {
        int i = u >> 3, ujl = (u >> 2) & 1, nh = u & 3;
        s_Wp[u] = Wh[(size_t)(cid * 2 + ujl) * NHH + nh * H + i];
    }

    float bsum = 0.f, myc = 0.f;
    int mylen = 0;
    if (tid < 128) {
        bsum = bi[j] + bhb[j];
        mylen = input_len[b];
        // cand(0) = tanh(P[0] + bias)   (z = 0); tag = 0
        myc = tanhf(g_P[(size_t)j * B + b] + bsum);
        __stcg(&g_cand[0][j * B + b], (unsigned long long)__float_as_uint(myc));
    }
    __syncthreads();                       // s_Wp visible CTA-wide

    float z0 = 0.f, z1 = 0.f, z2 = 0.f, z3 = 0.f;
    float h0 = 0.f, h1 = 0.f, h2 = 0.f, h3 = 0.f;

    #pragma unroll 1
    for (int t = 0; t < S; ++t) {
        const int p = t & 1;
        const unsigned tagw = (unsigned)t;

        // tail-thread prefetches (overlap the cand load stream)
        float pnext = 0.0f;
        float4 g4 = make_float4(0.f, 0.f, 0.f, 0.f);
        if (tid < 128) {
            if (t < S - 1)
                pnext = g_P[(size_t)(t + 1) * (H * B) + (size_t)j * B + b];
            g4 = *(const float4*)&g_gate[(size_t)t * (B * NH) + b * 4];
        }

        // partial y over our 32 cand rows, both jl at once; tag-checked loads
        float a0 = 0.f, a1 = 0.f, a2 = 0.f, a3 = 0.f;   // jl = 0
        float c0 = 0.f, c1 = 0.f, c2 = 0.f, c3 = 0.f;   // jl = 1
        const unsigned long long* cb = g_cand[p] + (g << 5) * B + b;
        const float4* wb = (const float4*)&s_Wp[(g << 5) * 8];
        #pragma unroll 8
        for (int k = 0; k < 32; ++k) {
            unsigned long long v = __ldcg(cb + k * B);
            if ((unsigned)(v >> 32) != tagw) {           // rare: not ready yet
                const volatile unsigned long long* vp = cb + k * B;
                do { v = *vp; } while ((unsigned)(v >> 32) != tagw);
            }
            float cv = __uint_as_float((unsigned)v);
            float4 wA = wb[k * 2];          // warp-broadcast LDS.128
            float4 wB = wb[k * 2 + 1];
            a0 = fmaf(wA.x, cv, a0); a1 = fmaf(wA.y, cv, a1);
            a2 = fmaf(wA.z, cv, a2); a3 = fmaf(wA.w, cv, a3);
            c0 = fmaf(wB.x, cv, c0); c1 = fmaf(wB.y, cv, c1);
            c2 = fmaf(wB.z, cv, c2); c3 = fmaf(wB.w, cv, c3);
        }
        *(float4*)&s_y[p][g][b][0]      = make_float4(a0, a1, a2, a3);
        *(float4*)&s_y[p][g][64 + b][0] = make_float4(c0, c1, c2, c3);
        __syncthreads();    // partials of step t visible; parity buffer keeps
                            // step t+1 writers off this slot (skew < 2 steps)

        if (tid < 128) {
            float y0 = 0.f, y1 = 0.f, y2 = 0.f, y3 = 0.f;
            #pragma unroll
            for (int gg = 0; gg < 8; ++gg) {
                float4 yv = *(const float4*)&s_y[p][gg][jl * 64 + b][0];
                y0 += yv.x; y1 += yv.y; y2 += yv.z; y3 += yv.w;
            }
            z0 = fmaf(g4.x, y0 - z0, z0);        // z' = z + g*(y - z)
            z1 = fmaf(g4.y, y1 - z1, z1);
            z2 = fmaf(g4.z, y2 - z2, z2);
            z3 = fmaf(g4.w, y3 - z3, z3);
            h0 = fmaf(g4.x, myc - h0, h0);       // h' = h + g*(cand - h)
            h1 = fmaf(g4.y, myc - h1, h1);
            h2 = fmaf(g4.z, myc - h2, h2);
            h3 = fmaf(g4.w, myc - h3, h3);

            if (t == mylen - 1) {
                g_sel[b * NHH + 0 * H + j] = h0;
                g_sel[b * NHH + 1 * H + j] = h1;
                g_sel[b * NHH + 2 * H + j] = h2;
                g_sel[b * NHH + 3 * H + j] = h3;
            }
            if (t < S - 1) {
                myc = tanhf(pnext + bsum + z0 + z1 + z2 + z3);
                unsigned long long pk =
                    ((unsigned long long)(unsigned)(t + 1) << 32) |
                    (unsigned long long)__float_as_uint(myc);
                __stcg(&g_cand[(t + 1) & 1][j * B + b], pk);
            }
        }
    }
}

// ---------------- readout ---------------------------------------------------
__global__ __launch_bounds__(256)
void final_fc_kernel(const float* __restrict__ fc1_W,
                     const float* __restrict__ fc1_b,
                     const float* __restrict__ fc2_W,
                     const float* __restrict__ fc2_b,
                     float* __restrict__ out) {
    __shared__ float selsh[NHH];
    __shared__ float red0[H];
    __shared__ float red1[H];
    const int b = blockIdx.x;
    const int j = threadIdx.x;

    #pragma unroll
    for (int i = 0; i < NH; ++i)
        selsh[i * H + j] = g_sel[b * NHH + i * H + j];
    __syncthreads();

    float s = fc1_b[j];
    const float4* w = (const float4*)(fc1_W + (size_t)j * NHH);
    #pragma unroll 4
    for (int k4 = 0; k4 < NHH / 4; ++k4) {
        float4 wv = w[k4];
        float4 sv = *(const float4*)&selsh[k4 * 4];
        s = fmaf(wv.x, sv.x, s);
        s = fmaf(wv.y, sv.y, s);
        s = fmaf(wv.z, sv.z, s);
        s = fmaf(wv.w, sv.w, s);
    }
    s = tanhf(s);
    red0[j] = s * fc2_W[j];
    red1[j] = s * fc2_W[H + j];
    __syncthreads();

    for (int stride = 128; stride >= 1; stride >>= 1) {
        if (j < stride) {
            red0[j] += red0[j + stride];
            red1[j] += red1[j + stride];
        }
        __syncthreads();
    }
    if (j == 0) {
        out[b * 2 + 0] = red0[0] + fc2_b[0];
        out[b * 2 + 1] = red1[0] + fc2_b[1];
    }
}

// ---------------------------------------------------------------------------
extern "C" void kernel_launch(void* const* d_in, const int* in_sizes, int n_in,
                              void* d_out, int out_size) {
    const int*   src       = (const int*)  d_in[0];
    const int*   input_len = (const int*)  d_in[1];
    const float* fix_src   = (const float*)d_in[2];
    const float* emb_table = (const float*)d_in[3];
    const float* Wi        = (const float*)d_in[4];
    const float* bi        = (const float*)d_in[5];
    const float* Wh        = (const float*)d_in[6];
    const float* bh        = (const float*)d_in[7];
    const float* fc1_W     = (const float*)d_in[8];
    const float* fc1_b     = (const float*)d_in[9];
    const float* fc2_W     = (const float*)d_in[10];
    const float* fc2_b     = (const float*)d_in[11];
    float* out = (float*)d_out;

    init_kernel<<<64, 256>>>();                 // clear cand tags (replay-safe)
    gate_kernel<<<S, 256>>>(fix_src);
    p_kernel<<<2 * S, 256>>>(src, emb_table, Wi);
    rnn_kernel<<<NCTA, 512>>>(input_len, bi, bh, Wh);
    final_fc_kernel<<<B, 256>>>(fc1_W, fc1_b, fc2_W, fc2_b, out);
}